// round 1
// baseline (speedup 1.0000x reference)
#include <cuda_runtime.h>
#include <math.h>

#define TLEN 8192
#define NTH  1024
#define EPT  (TLEN / NTH)   // 8 elements per thread in prep

// Scratch in device globals (no allocation allowed in kernel_launch).
__device__ float  g_a[TLEN];
__device__ float  g_b[TLEN];
__device__ float  g_w[TLEN];
__device__ double g_l2[TLEN];
__device__ double g_l1[TLEN];
__device__ float4 g_k4[TLEN / 4];   // final kernel k (with 1/W folded in), 16B aligned

__device__ __forceinline__ float squashf(float v, float lo, float hi) {
    float s = 1.0f / (1.0f + __expf(-v) * 0.0f + expf(-v)); // use accurate expf
    return lo + (hi - lo) * s;
}

// ---------------------------------------------------------------------------
// Kernel A: build coefficients a,b,w; run the two reverse affine scans for the
// adjoint variables; emit k_t / W as float4 array. Single block, 1024 threads.
// ---------------------------------------------------------------------------
__global__ void __launch_bounds__(NTH) prep_kernel(
    const float* fsn, const float* fin, const float* fdn, const float* ftn,
    const float* won, const float* wtn, const void* Fin)
{
    __shared__ double sA[NTH];
    __shared__ double sB[NTH];
    const int tid = threadIdx.x;

    // F is an int scalar (44100) in the reference; guard against float encoding.
    int   Fi = *(const int*)Fin;
    float Ff = *(const float*)Fin;
    double F = (Fi > 0 && Fi < 100000000) ? (double)Fi : (double)Ff;

    const float f_start = squashf(*fsn, 200.0f, 4000.0f);
    const float f_inf   = squashf(*fin, 20.0f, 500.0f);
    const float f_decay = squashf(*fdn, 0.0f, 2.0f);
    const float f_T     = squashf(*ftn, 0.0f, 2.0f);
    const float w_off   = squashf(*won, 0.0f, 1.0f);
    const float w_T     = squashf(*wtn, 0.01f, 0.5f);

    const float c      = (float)(sqrt(cbrt(2.0) - 1.0) * F / M_PI);
    const float base   = 0.7f * powf(0.1f, f_decay);
    const float lbase  = logf(base);
    const float escale = 1.0f / (10.0f * powf(0.1f, f_T));
    const float inv_wT = 1.0f / w_T;

    // --- coefficients -----------------------------------------------------
    #pragma unroll
    for (int j = 0; j < EPT; j++) {
        int i = tid * EPT + j;
        float t = (float)i * (1.0f / (float)TLEN);
        float f = f_inf + (f_start - f_inf) * expf(lbase * (t * escale));
        float w = 1.0f / (1.0f + expf(-(t - w_off) * inv_wT));
        float a = (f - c) / (f + c);
        g_a[i] = a;
        g_b[i] = 0.5f * (a + 1.0f);
        g_w[i] = w;
    }
    __syncthreads();

    // --- scan 1: lambda2 (reverse in t => forward in s = TLEN-1-t) --------
    // element s: h_s = A_s * h_{s-1} + B_s
    {
        double Ac = 1.0, Bc = 0.0;
        #pragma unroll
        for (int j = 0; j < EPT; j++) {
            int s = tid * EPT + j;
            int t = TLEN - 1 - s;
            double Ae, Be;
            if (s == 0)              { Ae = 0.0;               Be = (double)g_w[TLEN - 1]; }
            else if (s == TLEN - 1)  { Ae = -(double)g_a[1];   Be = 0.0; }
            else                     { Ae = -(double)g_a[t+1]; Be = (double)g_w[t]; }
            Bc = Ae * Bc + Be;
            Ac = Ae * Ac;
        }
        sA[tid] = Ac; sB[tid] = Bc;
        __syncthreads();
        for (int off = 1; off < NTH; off <<= 1) {
            double aL = 1.0, bL = 0.0;
            bool has = (tid >= off);
            if (has) { aL = sA[tid - off]; bL = sB[tid - off]; }
            __syncthreads();
            if (has) {
                double ao = sA[tid], bo = sB[tid];
                sA[tid] = ao * aL;
                sB[tid] = ao * bL + bo;
            }
            __syncthreads();
        }
        double h = (tid > 0) ? sB[tid - 1] : 0.0;
        #pragma unroll
        for (int j = 0; j < EPT; j++) {
            int s = tid * EPT + j;
            int t = TLEN - 1 - s;
            double Ae, Be;
            if (s == 0)              { Ae = 0.0;               Be = (double)g_w[TLEN - 1]; }
            else if (s == TLEN - 1)  { Ae = -(double)g_a[1];   Be = 0.0; }
            else                     { Ae = -(double)g_a[t+1]; Be = (double)g_w[t]; }
            h = Ae * h + Be;
            g_l2[t] = h;
        }
        __syncthreads();
    }

    // --- scan 2: lambda1 --------------------------------------------------
    {
        double Ac = 1.0, Bc = 0.0;
        #pragma unroll
        for (int j = 0; j < EPT; j++) {
            int s = tid * EPT + j;
            int t = TLEN - 1 - s;
            double Ae, Be;
            if (s == 0) {
                Ae = 0.0;
                Be = (double)g_b[TLEN-1] * g_l2[TLEN-1];
            } else if (s == TLEN - 1) {
                Ae = -(double)g_a[1];
                Be = (double)g_b[1] * g_l2[1];
            } else {
                Ae = -(double)g_a[t+1];
                Be = (double)g_b[t] * g_l2[t] + (double)g_b[t+1] * g_l2[t+1];
            }
            Bc = Ae * Bc + Be;
            Ac = Ae * Ac;
        }
        sA[tid] = Ac; sB[tid] = Bc;
        __syncthreads();
        for (int off = 1; off < NTH; off <<= 1) {
            double aL = 1.0, bL = 0.0;
            bool has = (tid >= off);
            if (has) { aL = sA[tid - off]; bL = sB[tid - off]; }
            __syncthreads();
            if (has) {
                double ao = sA[tid], bo = sB[tid];
                sA[tid] = ao * aL;
                sB[tid] = ao * bL + bo;
            }
            __syncthreads();
        }
        double h = (tid > 0) ? sB[tid - 1] : 0.0;
        #pragma unroll
        for (int j = 0; j < EPT; j++) {
            int s = tid * EPT + j;
            int t = TLEN - 1 - s;
            double Ae, Be;
            if (s == 0) {
                Ae = 0.0;
                Be = (double)g_b[TLEN-1] * g_l2[TLEN-1];
            } else if (s == TLEN - 1) {
                Ae = -(double)g_a[1];
                Be = (double)g_b[1] * g_l2[1];
            } else {
                Ae = -(double)g_a[t+1];
                Be = (double)g_b[t] * g_l2[t] + (double)g_b[t+1] * g_l2[t+1];
            }
            h = Ae * h + Be;
            g_l1[t] = h;
        }
        __syncthreads();
    }

    // --- W = sum(w) -------------------------------------------------------
    {
        double ws = 0.0;
        #pragma unroll
        for (int j = 0; j < EPT; j++) ws += (double)g_w[tid * EPT + j];
        sA[tid] = ws;
        __syncthreads();
        for (int off = NTH / 2; off > 0; off >>= 1) {
            if (tid < off) sA[tid] += sA[tid + off];
            __syncthreads();
        }
        double invW = 1.0 / sA[0];

        // --- emit k_t * invW ---------------------------------------------
        float* kf = (float*)g_k4;
        #pragma unroll
        for (int j = 0; j < EPT; j++) {
            int i = tid * EPT + j;
            double kv;
            if (i == 0) {
                kv = (double)g_w[0] + (double)g_b[1] * g_l1[1] + g_l1[0] + g_l2[0];
            } else if (i == TLEN - 1) {
                kv = (double)g_b[i] * g_l1[i];
            } else {
                kv = (double)g_b[i] * g_l1[i] + (double)g_b[i+1] * g_l1[i+1];
            }
            kf[i] = (float)(kv * invW);
        }
    }
}

// ---------------------------------------------------------------------------
// Kernel B: out[row] = dot(X[row,:], k).  One block per row, float4 loads.
// ---------------------------------------------------------------------------
__global__ void __launch_bounds__(256) gemv_kernel(
    const float* __restrict__ X, float* __restrict__ out)
{
    const int row = blockIdx.x;
    const float4* __restrict__ xr = (const float4*)(X + (size_t)row * TLEN);

    float acc = 0.0f;
    #pragma unroll
    for (int i = 0; i < TLEN / 4 / 256; i++) {
        int idx = i * 256 + threadIdx.x;
        float4 x = xr[idx];
        float4 k = g_k4[idx];
        acc = fmaf(x.x, k.x, acc);
        acc = fmaf(x.y, k.y, acc);
        acc = fmaf(x.z, k.z, acc);
        acc = fmaf(x.w, k.w, acc);
    }

    // warp reduce
    #pragma unroll
    for (int off = 16; off > 0; off >>= 1)
        acc += __shfl_down_sync(0xffffffffu, acc, off);

    __shared__ float sred[8];
    int w = threadIdx.x >> 5, l = threadIdx.x & 31;
    if (l == 0) sred[w] = acc;
    __syncthreads();
    if (threadIdx.x == 0) {
        float s = 0.0f;
        #pragma unroll
        for (int i = 0; i < 8; i++) s += sred[i];
        out[row] = s;
    }
}

extern "C" void kernel_launch(void* const* d_in, const int* in_sizes, int n_in,
                              void* d_out, int out_size)
{
    const float* X = (const float*)d_in[0];
    const void*  F = d_in[1];

    prep_kernel<<<1, NTH>>>(
        (const float*)d_in[2], (const float*)d_in[3], (const float*)d_in[4],
        (const float*)d_in[5], (const float*)d_in[6], (const float*)d_in[7], F);

    int rows = in_sizes[0] / TLEN;
    gemv_kernel<<<rows, 256>>>(X, (float*)d_out);
}

// round 2
// speedup vs baseline: 2.3993x; 2.3993x over previous
#include <cuda_runtime.h>
#include <math.h>

#define TLEN 8192
#define NTH  1024
#define EPT  (TLEN / NTH)   // 8 elements per thread in prep

// Scratch in device globals (no allocation allowed in kernel_launch).
__device__ float  g_a[TLEN];
__device__ float  g_b[TLEN];
__device__ float  g_w[TLEN];
__device__ float  g_l2[TLEN];
__device__ float  g_l1[TLEN];
__device__ float4 g_k4[TLEN / 4];   // final kernel k (with 1/W folded in)

__device__ __forceinline__ float squashf(float v, float lo, float hi) {
    float s = 1.0f / (1.0f + expf(-v));
    return lo + (hi - lo) * s;
}

// ---------------------------------------------------------------------------
// Kernel A: build coefficients a,b,w; run two reverse affine scans for the
// adjoint variables; emit k_t / W. Single block, 1024 threads, ALL FP32.
// ---------------------------------------------------------------------------
__global__ void __launch_bounds__(NTH) prep_kernel(
    const float* fsn, const float* fin, const float* fdn, const float* ftn,
    const float* won, const float* wtn, const void* Fin)
{
    __shared__ float sA[NTH];
    __shared__ float sB[NTH];
    const int tid = threadIdx.x;

    // F is an int scalar (44100); guard against float encoding.
    int   Fi = *(const int*)Fin;
    float Ff = *(const float*)Fin;
    float F = (Fi > 0 && Fi < 100000000) ? (float)Fi : Ff;

    const float f_start = squashf(*fsn, 200.0f, 4000.0f);
    const float f_inf   = squashf(*fin, 20.0f, 500.0f);
    const float f_decay = squashf(*fdn, 0.0f, 2.0f);
    const float f_T     = squashf(*ftn, 0.0f, 2.0f);
    const float w_off   = squashf(*won, 0.0f, 1.0f);
    const float w_T     = squashf(*wtn, 0.01f, 0.5f);

    // (2^(1/3)-1)^0.5 = 0.5098245285339035
    const float c      = 0.5098245285339035f * F * (float)(1.0 / M_PI);
    const float lbase  = logf(0.7f * powf(0.1f, f_decay));
    const float escale = 1.0f / (10.0f * powf(0.1f, f_T));
    const float inv_wT = 1.0f / w_T;

    // --- coefficients -----------------------------------------------------
    #pragma unroll
    for (int j = 0; j < EPT; j++) {
        int i = tid * EPT + j;
        float t = (float)i * (1.0f / (float)TLEN);
        float f = f_inf + (f_start - f_inf) * expf(lbase * (t * escale));
        float w = 1.0f / (1.0f + expf(-(t - w_off) * inv_wT));
        float a = (f - c) / (f + c);
        g_a[i] = a;
        g_b[i] = 0.5f * (a + 1.0f);
        g_w[i] = w;
    }
    __syncthreads();

    // --- scan 1: lambda2 (reverse in t => forward in s = TLEN-1-t) --------
    {
        float Ac = 1.0f, Bc = 0.0f;
        #pragma unroll
        for (int j = 0; j < EPT; j++) {
            int s = tid * EPT + j;
            int t = TLEN - 1 - s;
            float Ae, Be;
            if (s == 0)              { Ae = 0.0f;       Be = g_w[TLEN - 1]; }
            else if (s == TLEN - 1)  { Ae = -g_a[1];    Be = 0.0f; }
            else                     { Ae = -g_a[t+1];  Be = g_w[t]; }
            Bc = fmaf(Ae, Bc, Be);
            Ac = Ae * Ac;
        }
        sA[tid] = Ac; sB[tid] = Bc;
        __syncthreads();
        for (int off = 1; off < NTH; off <<= 1) {
            float aL = 1.0f, bL = 0.0f;
            bool has = (tid >= off);
            if (has) { aL = sA[tid - off]; bL = sB[tid - off]; }
            __syncthreads();
            if (has) {
                float ao = sA[tid], bo = sB[tid];
                sA[tid] = ao * aL;
                sB[tid] = fmaf(ao, bL, bo);
            }
            __syncthreads();
        }
        float h = (tid > 0) ? sB[tid - 1] : 0.0f;
        #pragma unroll
        for (int j = 0; j < EPT; j++) {
            int s = tid * EPT + j;
            int t = TLEN - 1 - s;
            float Ae, Be;
            if (s == 0)              { Ae = 0.0f;       Be = g_w[TLEN - 1]; }
            else if (s == TLEN - 1)  { Ae = -g_a[1];    Be = 0.0f; }
            else                     { Ae = -g_a[t+1];  Be = g_w[t]; }
            h = fmaf(Ae, h, Be);
            g_l2[t] = h;
        }
        __syncthreads();
    }

    // --- scan 2: lambda1 --------------------------------------------------
    {
        float Ac = 1.0f, Bc = 0.0f;
        #pragma unroll
        for (int j = 0; j < EPT; j++) {
            int s = tid * EPT + j;
            int t = TLEN - 1 - s;
            float Ae, Be;
            if (s == 0) {
                Ae = 0.0f;
                Be = g_b[TLEN-1] * g_l2[TLEN-1];
            } else if (s == TLEN - 1) {
                Ae = -g_a[1];
                Be = g_b[1] * g_l2[1];
            } else {
                Ae = -g_a[t+1];
                Be = fmaf(g_b[t], g_l2[t], g_b[t+1] * g_l2[t+1]);
            }
            Bc = fmaf(Ae, Bc, Be);
            Ac = Ae * Ac;
        }
        sA[tid] = Ac; sB[tid] = Bc;
        __syncthreads();
        for (int off = 1; off < NTH; off <<= 1) {
            float aL = 1.0f, bL = 0.0f;
            bool has = (tid >= off);
            if (has) { aL = sA[tid - off]; bL = sB[tid - off]; }
            __syncthreads();
            if (has) {
                float ao = sA[tid], bo = sB[tid];
                sA[tid] = ao * aL;
                sB[tid] = fmaf(ao, bL, bo);
            }
            __syncthreads();
        }
        float h = (tid > 0) ? sB[tid - 1] : 0.0f;
        #pragma unroll
        for (int j = 0; j < EPT; j++) {
            int s = tid * EPT + j;
            int t = TLEN - 1 - s;
            float Ae, Be;
            if (s == 0) {
                Ae = 0.0f;
                Be = g_b[TLEN-1] * g_l2[TLEN-1];
            } else if (s == TLEN - 1) {
                Ae = -g_a[1];
                Be = g_b[1] * g_l2[1];
            } else {
                Ae = -g_a[t+1];
                Be = fmaf(g_b[t], g_l2[t], g_b[t+1] * g_l2[t+1]);
            }
            h = fmaf(Ae, h, Be);
            g_l1[t] = h;
        }
        __syncthreads();
    }

    // --- W = sum(w) -------------------------------------------------------
    {
        float ws = 0.0f;
        #pragma unroll
        for (int j = 0; j < EPT; j++) ws += g_w[tid * EPT + j];
        sA[tid] = ws;
        __syncthreads();
        for (int off = NTH / 2; off > 0; off >>= 1) {
            if (tid < off) sA[tid] += sA[tid + off];
            __syncthreads();
        }
        float invW = 1.0f / sA[0];

        // --- emit k_t * invW ---------------------------------------------
        float* kf = (float*)g_k4;
        #pragma unroll
        for (int j = 0; j < EPT; j++) {
            int i = tid * EPT + j;
            float kv;
            if (i == 0) {
                kv = g_w[0] + fmaf(g_b[1], g_l1[1], g_l1[0] + g_l2[0]);
            } else if (i == TLEN - 1) {
                kv = g_b[i] * g_l1[i];
            } else {
                kv = fmaf(g_b[i], g_l1[i], g_b[i+1] * g_l1[i+1]);
            }
            kf[i] = kv * invW;
        }
    }
}

// ---------------------------------------------------------------------------
// Kernel B: out[row] = dot(X[row,:], k).  One block (128 thr) per row.
// 16 CTAs/SM -> 2048 blocks fit in a single wave on 148 SMs.
// ---------------------------------------------------------------------------
__global__ void __launch_bounds__(128, 16) gemv_kernel(
    const float* __restrict__ X, float* __restrict__ out)
{
    const int row = blockIdx.x;
    const float4* __restrict__ xr = (const float4*)(X + (size_t)row * TLEN);

    float acc = 0.0f;
    #pragma unroll
    for (int i = 0; i < TLEN / 4 / 128; i++) {   // 16 iterations
        int idx = i * 128 + threadIdx.x;
        float4 x = __ldcs(&xr[idx]);             // streaming: X is read-once
        float4 k = g_k4[idx];                    // L1-resident across CTAs
        acc = fmaf(x.x, k.x, acc);
        acc = fmaf(x.y, k.y, acc);
        acc = fmaf(x.z, k.z, acc);
        acc = fmaf(x.w, k.w, acc);
    }

    // warp reduce
    #pragma unroll
    for (int off = 16; off > 0; off >>= 1)
        acc += __shfl_down_sync(0xffffffffu, acc, off);

    __shared__ float sred[4];
    int w = threadIdx.x >> 5, l = threadIdx.x & 31;
    if (l == 0) sred[w] = acc;
    __syncthreads();
    if (threadIdx.x == 0)
        out[row] = (sred[0] + sred[1]) + (sred[2] + sred[3]);
}

extern "C" void kernel_launch(void* const* d_in, const int* in_sizes, int n_in,
                              void* d_out, int out_size)
{
    const float* X = (const float*)d_in[0];
    const void*  F = d_in[1];

    prep_kernel<<<1, NTH>>>(
        (const float*)d_in[2], (const float*)d_in[3], (const float*)d_in[4],
        (const float*)d_in[5], (const float*)d_in[6], (const float*)d_in[7], F);

    int rows = in_sizes[0] / TLEN;
    gemv_kernel<<<rows, 128>>>(X, (float*)d_out);
}

// round 3
// speedup vs baseline: 2.4203x; 1.0087x over previous
#include <cuda_runtime.h>
#include <math.h>

#define TLEN 8192
#define NTH  1024
#define EPT  (TLEN / NTH)   // 8 elements per thread in prep

// Scratch in device globals (no allocation allowed in kernel_launch).
__device__ float  g_a[TLEN];
__device__ float  g_b[TLEN];
__device__ float  g_w[TLEN];
__device__ float  g_l2[TLEN];
__device__ float  g_l1[TLEN];
__device__ float4 g_k4[TLEN / 4];   // final kernel k (with 1/W folded in)

__device__ __forceinline__ float squashf(float v, float lo, float hi) {
    float s = 1.0f / (1.0f + __expf(-v));
    return lo + (hi - lo) * s;
}

// ---------------------------------------------------------------------------
// Kernel A: build coefficients a,b,w; run two reverse affine scans for the
// adjoint variables; emit k_t / W. Single block, 1024 threads, FP32 + MUFU.
// ---------------------------------------------------------------------------
__global__ void __launch_bounds__(NTH) prep_kernel(
    const float* fsn, const float* fin, const float* fdn, const float* ftn,
    const float* won, const float* wtn, const void* Fin)
{
    __shared__ float sA[NTH];
    __shared__ float sB[NTH];
    const int tid = threadIdx.x;

    // F is an int scalar (44100); guard against float encoding.
    int   Fi = *(const int*)Fin;
    float Ff = *(const float*)Fin;
    float F = (Fi > 0 && Fi < 100000000) ? (float)Fi : Ff;

    const float f_start = squashf(*fsn, 200.0f, 4000.0f);
    const float f_inf   = squashf(*fin, 20.0f, 500.0f);
    const float f_decay = squashf(*fdn, 0.0f, 2.0f);
    const float f_T     = squashf(*ftn, 0.0f, 2.0f);
    const float w_off   = squashf(*won, 0.0f, 1.0f);
    const float w_T     = squashf(*wtn, 0.01f, 0.5f);

    // (2^(1/3)-1)^0.5 = 0.5098245285339035
    const float c      = 0.5098245285339035f * F * (float)(1.0 / M_PI);
    // log(0.7 * 0.1^f_decay) = log(0.7) - f_decay*log(10)
    const float lbase  = -0.35667494393873245f - f_decay * 2.302585092994046f;
    // 1 / (10 * 0.1^f_T) = 0.1 * 10^f_T
    const float escale = 0.1f * __expf(f_T * 2.302585092994046f);
    const float inv_wT = 1.0f / w_T;

    // --- coefficients -----------------------------------------------------
    #pragma unroll
    for (int j = 0; j < EPT; j++) {
        int i = tid * EPT + j;
        float t = (float)i * (1.0f / (float)TLEN);
        float f = f_inf + (f_start - f_inf) * __expf(lbase * (t * escale));
        float w = 1.0f / (1.0f + __expf(-(t - w_off) * inv_wT));
        float a = (f - c) / (f + c);
        g_a[i] = a;
        g_b[i] = 0.5f * (a + 1.0f);
        g_w[i] = w;
    }
    __syncthreads();

    // --- scan 1: lambda2 (reverse in t => forward in s = TLEN-1-t) --------
    {
        float Ac = 1.0f, Bc = 0.0f;
        #pragma unroll
        for (int j = 0; j < EPT; j++) {
            int s = tid * EPT + j;
            int t = TLEN - 1 - s;
            float Ae, Be;
            if (s == 0)              { Ae = 0.0f;       Be = g_w[TLEN - 1]; }
            else if (s == TLEN - 1)  { Ae = -g_a[1];    Be = 0.0f; }
            else                     { Ae = -g_a[t+1];  Be = g_w[t]; }
            Bc = fmaf(Ae, Bc, Be);
            Ac = Ae * Ac;
        }
        sA[tid] = Ac; sB[tid] = Bc;
        __syncthreads();
        for (int off = 1; off < NTH; off <<= 1) {
            float aL = 1.0f, bL = 0.0f;
            bool has = (tid >= off);
            if (has) { aL = sA[tid - off]; bL = sB[tid - off]; }
            __syncthreads();
            if (has) {
                float ao = sA[tid], bo = sB[tid];
                sA[tid] = ao * aL;
                sB[tid] = fmaf(ao, bL, bo);
            }
            __syncthreads();
        }
        float h = (tid > 0) ? sB[tid - 1] : 0.0f;
        #pragma unroll
        for (int j = 0; j < EPT; j++) {
            int s = tid * EPT + j;
            int t = TLEN - 1 - s;
            float Ae, Be;
            if (s == 0)              { Ae = 0.0f;       Be = g_w[TLEN - 1]; }
            else if (s == TLEN - 1)  { Ae = -g_a[1];    Be = 0.0f; }
            else                     { Ae = -g_a[t+1];  Be = g_w[t]; }
            h = fmaf(Ae, h, Be);
            g_l2[t] = h;
        }
        __syncthreads();
    }

    // --- scan 2: lambda1 --------------------------------------------------
    {
        float Ac = 1.0f, Bc = 0.0f;
        #pragma unroll
        for (int j = 0; j < EPT; j++) {
            int s = tid * EPT + j;
            int t = TLEN - 1 - s;
            float Ae, Be;
            if (s == 0) {
                Ae = 0.0f;
                Be = g_b[TLEN-1] * g_l2[TLEN-1];
            } else if (s == TLEN - 1) {
                Ae = -g_a[1];
                Be = g_b[1] * g_l2[1];
            } else {
                Ae = -g_a[t+1];
                Be = fmaf(g_b[t], g_l2[t], g_b[t+1] * g_l2[t+1]);
            }
            Bc = fmaf(Ae, Bc, Be);
            Ac = Ae * Ac;
        }
        sA[tid] = Ac; sB[tid] = Bc;
        __syncthreads();
        for (int off = 1; off < NTH; off <<= 1) {
            float aL = 1.0f, bL = 0.0f;
            bool has = (tid >= off);
            if (has) { aL = sA[tid - off]; bL = sB[tid - off]; }
            __syncthreads();
            if (has) {
                float ao = sA[tid], bo = sB[tid];
                sA[tid] = ao * aL;
                sB[tid] = fmaf(ao, bL, bo);
            }
            __syncthreads();
        }
        float h = (tid > 0) ? sB[tid - 1] : 0.0f;
        #pragma unroll
        for (int j = 0; j < EPT; j++) {
            int s = tid * EPT + j;
            int t = TLEN - 1 - s;
            float Ae, Be;
            if (s == 0) {
                Ae = 0.0f;
                Be = g_b[TLEN-1] * g_l2[TLEN-1];
            } else if (s == TLEN - 1) {
                Ae = -g_a[1];
                Be = g_b[1] * g_l2[1];
            } else {
                Ae = -g_a[t+1];
                Be = fmaf(g_b[t], g_l2[t], g_b[t+1] * g_l2[t+1]);
            }
            h = fmaf(Ae, h, Be);
            g_l1[t] = h;
        }
        __syncthreads();
    }

    // --- W = sum(w) -------------------------------------------------------
    {
        float ws = 0.0f;
        #pragma unroll
        for (int j = 0; j < EPT; j++) ws += g_w[tid * EPT + j];
        sA[tid] = ws;
        __syncthreads();
        for (int off = NTH / 2; off > 0; off >>= 1) {
            if (tid < off) sA[tid] += sA[tid + off];
            __syncthreads();
        }
        float invW = 1.0f / sA[0];

        // --- emit k_t * invW ---------------------------------------------
        float* kf = (float*)g_k4;
        #pragma unroll
        for (int j = 0; j < EPT; j++) {
            int i = tid * EPT + j;
            float kv;
            if (i == 0) {
                kv = g_w[0] + fmaf(g_b[1], g_l1[1], g_l1[0] + g_l2[0]);
            } else if (i == TLEN - 1) {
                kv = g_b[i] * g_l1[i];
            } else {
                kv = fmaf(g_b[i], g_l1[i], g_b[i+1] * g_l1[i+1]);
            }
            kf[i] = kv * invW;
        }
    }
}

// ---------------------------------------------------------------------------
// Kernel B: out[row] = dot(X[row,:], k).  One block (256 thr) per row.
// All 8 x-loads + 8 k-loads issued BEFORE the FMA block -> high MLP,
// enough bytes-in-flight per SM to cover DRAM latency.
// ---------------------------------------------------------------------------
__global__ void __launch_bounds__(256) gemv_kernel(
    const float* __restrict__ X, float* __restrict__ out)
{
    const int row = blockIdx.x;
    const float4* __restrict__ xr = (const float4*)(X + (size_t)row * TLEN);

    float4 x[8];
    float4 k[8];
    #pragma unroll
    for (int i = 0; i < 8; i++)
        x[i] = __ldcs(&xr[i * 256 + threadIdx.x]);   // streaming: X is read-once
    #pragma unroll
    for (int i = 0; i < 8; i++)
        k[i] = g_k4[i * 256 + threadIdx.x];          // L1-resident across CTAs

    float a0 = 0.0f, a1 = 0.0f, a2 = 0.0f, a3 = 0.0f;
    #pragma unroll
    for (int i = 0; i < 8; i++) {
        a0 = fmaf(x[i].x, k[i].x, a0);
        a1 = fmaf(x[i].y, k[i].y, a1);
        a2 = fmaf(x[i].z, k[i].z, a2);
        a3 = fmaf(x[i].w, k[i].w, a3);
    }
    float acc = (a0 + a1) + (a2 + a3);

    // warp reduce
    #pragma unroll
    for (int off = 16; off > 0; off >>= 1)
        acc += __shfl_down_sync(0xffffffffu, acc, off);

    __shared__ float sred[8];
    int w = threadIdx.x >> 5, l = threadIdx.x & 31;
    if (l == 0) sred[w] = acc;
    __syncthreads();
    if (threadIdx.x == 0) {
        float s = 0.0f;
        #pragma unroll
        for (int i = 0; i < 8; i++) s += sred[i];
        out[row] = s;
    }
}

extern "C" void kernel_launch(void* const* d_in, const int* in_sizes, int n_in,
                              void* d_out, int out_size)
{
    const float* X = (const float*)d_in[0];
    const void*  F = d_in[1];

    prep_kernel<<<1, NTH>>>(
        (const float*)d_in[2], (const float*)d_in[3], (const float*)d_in[4],
        (const float*)d_in[5], (const float*)d_in[6], (const float*)d_in[7], F);

    int rows = in_sizes[0] / TLEN;
    gemv_kernel<<<rows, 256>>>(X, (float*)d_out);
}

// round 4
// speedup vs baseline: 6.0897x; 2.5161x over previous
#include <cuda_runtime.h>
#include <math.h>

#define TLEN 8192
#define NTH  1024
#define EPT  8           // elements per thread in prep (NTH*EPT == TLEN)
#define NWARP (NTH/32)   // 32 warps

__device__ float4 g_k4[TLEN / 4];   // final kernel k (with 1/W folded in)

__device__ __forceinline__ float squashf(float v, float lo, float hi) {
    return lo + (hi - lo) / (1.0f + __expf(-v));
}

// ---------------------------------------------------------------------------
// Prep: compute k_t / W entirely in registers + warp shuffles.
//
// The forward IIR scan is linear in X, so out[row] = dot(k, X[row,:]) with k
// obtained from two reverse affine recurrences over the (t-only) coefficients:
//   lambda2, lambda1 (adjoints), then k_t = b_t*l1_t + b_{t+1}*l1_{t+1} (+ends).
// Reverse index s = TLEN-1-t; thread tid owns s in [tid*8, tid*8+8).
// Affine scan h_s = Ae_s * h_{s-1} + Be_s via (A,B) pair composition:
// serial-8 -> warp inclusive shfl scan -> warp0 scans 32 aggregates -> replay.
// ---------------------------------------------------------------------------
__global__ void __launch_bounds__(NTH) prep_kernel(
    const float* fsn, const float* fin, const float* fdn, const float* ftn,
    const float* won, const float* wtn, const void* Fin)
{
    __shared__ float sWA[NWARP];
    __shared__ float sWB[NWARP];
    __shared__ float sEx[NTH];

    const int tid  = threadIdx.x;
    const int lane = tid & 31;
    const int wid  = tid >> 5;

    // F is an int scalar (44100); guard against float encoding.
    int   Fi = *(const int*)Fin;
    float Ff = *(const float*)Fin;
    float F  = (Fi > 0 && Fi < 100000000) ? (float)Fi : Ff;

    const float f_start = squashf(*fsn, 200.0f, 4000.0f);
    const float f_inf   = squashf(*fin, 20.0f, 500.0f);
    const float f_decay = squashf(*fdn, 0.0f, 2.0f);
    const float f_T     = squashf(*ftn, 0.0f, 2.0f);
    const float w_off   = squashf(*won, 0.0f, 1.0f);
    const float w_T     = squashf(*wtn, 0.01f, 0.5f);

    // c = sqrt(2^(1/3)-1) * F / pi
    const float c      = 0.5098245285339035f * F * 0.3183098861837907f;
    // log(0.7*0.1^fd) ; 1/(10*0.1^fT) = 0.1*10^fT
    const float lbase  = -0.35667494393873245f - f_decay * 2.302585092994046f;
    const float escale = 0.1f * __expf(f_T * 2.302585092994046f);
    const float inv_wT = 1.0f / w_T;
    const float lk     = lbase * escale * (1.0f / (float)TLEN); // exp arg per t-index

    // t(j) = 8191 - 8*tid - j ;  tau(j) = t(j)+1 = 8192 - 8*tid - j
    // a at tau(0..8)  (tau(8) = t(7))  -- a(tau) used as a[t+1] for elem j,
    // and a(t(j)) = atau[j+1].
    float atau[EPT + 1];
    float wreg[EPT];
    const int tbase = TLEN - 1 - tid * EPT;   // t(0)
    #pragma unroll
    for (int j = 0; j <= EPT; j++) {
        float ti = (float)(tbase + 1 - j);    // tau(j)
        float f  = f_inf + (f_start - f_inf) * __expf(lk * ti);
        atau[j]  = (f - c) / (f + c);
    }
    float wsum = 0.0f;
    #pragma unroll
    for (int j = 0; j < EPT; j++) {
        float t = (float)(tbase - j) * (1.0f / (float)TLEN);
        wreg[j] = 1.0f / (1.0f + __expf(-(t - w_off) * inv_wT));
        wsum += wreg[j];
    }

    const bool first = (tid == 0);             // owns s=0   (t=8191)
    const bool last  = (tid == NTH - 1);       // owns s=8191 (t=0)

    float lreg[EPT];   // holds lambda2 after scan1, overwritten by lambda1

    // ===================== scan 1 : lambda2 ==============================
    {
        float A = 1.0f, B = 0.0f;
        #pragma unroll
        for (int j = 0; j < EPT; j++) {
            float Ae = (first && j == 0) ? 0.0f : -atau[j];
            float Be = (last  && j == EPT - 1) ? 0.0f : wreg[j];
            B = fmaf(Ae, B, Be);
            A = Ae * A;
        }
        // warp inclusive scan (compose: self after received)
        #pragma unroll
        for (int d = 1; d < 32; d <<= 1) {
            float pA = __shfl_up_sync(0xffffffffu, A, d);
            float pB = __shfl_up_sync(0xffffffffu, B, d);
            if (lane >= d) { B = fmaf(A, pB, B); A = A * pA; }
        }
        if (lane == 31) { sWA[wid] = A; sWB[wid] = B; }
        __syncthreads();
        if (wid == 0) {
            float a = sWA[lane], b = sWB[lane];
            #pragma unroll
            for (int d = 1; d < 32; d <<= 1) {
                float pA = __shfl_up_sync(0xffffffffu, a, d);
                float pB = __shfl_up_sync(0xffffffffu, b, d);
                if (lane >= d) { b = fmaf(a, pB, b); a = a * pA; }
            }
            sWA[lane] = a; sWB[lane] = b;
        }
        __syncthreads();
        // exclusive prefix for this thread: lane_excl o warp_excl
        float eA = __shfl_up_sync(0xffffffffu, A, 1);
        float eB = __shfl_up_sync(0xffffffffu, B, 1);
        if (lane == 0) { eA = 1.0f; eB = 0.0f; }
        float h;
        if (wid > 0) h = fmaf(eA, sWB[wid - 1], eB);
        else         h = eB;
        // replay
        #pragma unroll
        for (int j = 0; j < EPT; j++) {
            float Ae = (first && j == 0) ? 0.0f : -atau[j];
            float Be = (last  && j == EPT - 1) ? 0.0f : wreg[j];
            h = fmaf(Ae, h, Be);
            lreg[j] = h;                     // l2 at s = tid*8+j (t = tbase-j)
        }
    }

    // neighbor exchange: need prev thread's l2 (s-1) for our j=0
    sEx[tid] = lreg[EPT - 1];
    __syncthreads();
    float prevL2 = (tid > 0) ? sEx[tid - 1] : 0.0f;   // unused for tid 0
    __syncthreads();

    // ===================== scan 2 : lambda1 ==============================
    // Be(j) = b(t)*l2[t] + b(t+1)*l2[t+1]
    //   b(t) = 0.5*(atau[j+1]+1), b(t+1) = 0.5*(atau[j]+1)
    //   l2[t] = lreg[j], l2[t+1] = lreg[j-1] (j=0 -> prevL2)
    // ends: s=0 keeps only b(t) term; s=8191 keeps only b(t+1) term.
    float l2_last = lreg[EPT - 1];    // save before overwrite (tid 1023 needs it)
    {
        float A = 1.0f, B = 0.0f;
        #pragma unroll
        for (int j = 0; j < EPT; j++) {
            float bt  = 0.5f * (atau[j + 1] + 1.0f);
            float bt1 = 0.5f * (atau[j] + 1.0f);
            float l2c = lreg[j];
            float l2p = (j == 0) ? prevL2 : lreg[j - 1];
            float Be;
            if (first && j == 0)            Be = bt * l2c;
            else if (last && j == EPT - 1)  Be = bt1 * l2p;
            else                            Be = fmaf(bt, l2c, bt1 * l2p);
            float Ae = (first && j == 0) ? 0.0f : -atau[j];
            B = fmaf(Ae, B, Be);
            A = Ae * A;
        }
        #pragma unroll
        for (int d = 1; d < 32; d <<= 1) {
            float pA = __shfl_up_sync(0xffffffffu, A, d);
            float pB = __shfl_up_sync(0xffffffffu, B, d);
            if (lane >= d) { B = fmaf(A, pB, B); A = A * pA; }
        }
        if (lane == 31) { sWA[wid] = A; sWB[wid] = B; }
        __syncthreads();
        if (wid == 0) {
            float a = sWA[lane], b = sWB[lane];
            #pragma unroll
            for (int d = 1; d < 32; d <<= 1) {
                float pA = __shfl_up_sync(0xffffffffu, a, d);
                float pB = __shfl_up_sync(0xffffffffu, b, d);
                if (lane >= d) { b = fmaf(a, pB, b); a = a * pA; }
            }
            sWA[lane] = a; sWB[lane] = b;
        }
        __syncthreads();
        float eA = __shfl_up_sync(0xffffffffu, A, 1);
        float eB = __shfl_up_sync(0xffffffffu, B, 1);
        if (lane == 0) { eA = 1.0f; eB = 0.0f; }
        float h;
        if (wid > 0) h = fmaf(eA, sWB[wid - 1], eB);
        else         h = eB;
        // replay, overwriting lreg with l1 (keep the consumed l2 in a temp)
        float l2p = prevL2;
        #pragma unroll
        for (int j = 0; j < EPT; j++) {
            float bt  = 0.5f * (atau[j + 1] + 1.0f);
            float bt1 = 0.5f * (atau[j] + 1.0f);
            float l2c = lreg[j];
            float Be;
            if (first && j == 0)            Be = bt * l2c;
            else if (last && j == EPT - 1)  Be = bt1 * l2p;
            else                            Be = fmaf(bt, l2c, bt1 * l2p);
            float Ae = (first && j == 0) ? 0.0f : -atau[j];
            h = fmaf(Ae, h, Be);
            lreg[j] = h;                    // l1
            l2p = l2c;
        }
    }

    // neighbor exchange for l1
    __syncthreads();
    sEx[tid] = lreg[EPT - 1];
    __syncthreads();
    float prevL1 = (tid > 0) ? sEx[tid - 1] : 0.0f;

    // ===================== W = sum(w) ====================================
    #pragma unroll
    for (int d = 16; d > 0; d >>= 1)
        wsum += __shfl_down_sync(0xffffffffu, wsum, d);
    __syncthreads();
    if (lane == 0) sWA[wid] = wsum;
    __syncthreads();
    if (tid == 0) {
        float s = 0.0f;
        #pragma unroll
        for (int i = 0; i < NWARP; i++) s += sWA[i];
        sWB[0] = 1.0f / s;
    }
    __syncthreads();
    const float invW = sWB[0];

    // ===================== emit k ========================================
    // k(i=t(j)) = b(t)*l1[t] + b(t+1)*l1[t+1]  (general)
    //   i==TLEN-1 (tid0,j0):   only b(t)*l1[t]
    //   i==0 (tid1023,j7):     w[0] + b[1]*l1[1] + l1[0] + l2[0]
    float* kf = (float*)g_k4;
    #pragma unroll
    for (int j = 0; j < EPT; j++) {
        float bt  = 0.5f * (atau[j + 1] + 1.0f);
        float bt1 = 0.5f * (atau[j] + 1.0f);
        float l1c = lreg[j];
        float l1p = (j == 0) ? prevL1 : lreg[j - 1];
        float kv;
        if (first && j == 0) {
            kv = bt * l1c;
        } else if (last && j == EPT - 1) {
            // w(0) + b(1)*l1(1) + l1(0) + l2(0)
            kv = wreg[EPT - 1] + fmaf(bt1, lreg[EPT - 2], l1c + l2_last);
        } else {
            kv = fmaf(bt, l1c, bt1 * l1p);
        }
        kf[tbase - j] = kv * invW;
    }
}

// ---------------------------------------------------------------------------
// GEMV: 2 rows per CTA (grid = rows/2 = 1024 -> one uniform wave).
// Two independent row streams interleaved -> real MLP without fighting ptxas.
// ---------------------------------------------------------------------------
__global__ void __launch_bounds__(256) gemv_kernel(
    const float* __restrict__ X, float* __restrict__ out)
{
    const int r0 = blockIdx.x * 2;
    const float4* __restrict__ x0 = (const float4*)(X + (size_t)r0 * TLEN);
    const float4* __restrict__ x1 = (const float4*)(X + (size_t)(r0 + 1) * TLEN);

    float a00 = 0.0f, a01 = 0.0f, a10 = 0.0f, a11 = 0.0f;
    #pragma unroll
    for (int i = 0; i < TLEN / 4 / 256; i++) {   // 8 iterations
        int idx = i * 256 + threadIdx.x;
        float4 xa = __ldcs(&x0[idx]);            // streaming, read-once
        float4 xb = __ldcs(&x1[idx]);
        float4 kk = g_k4[idx];                   // L1/L2-resident
        a00 = fmaf(xa.x, kk.x, a00); a01 = fmaf(xa.y, kk.y, a01);
        a00 = fmaf(xa.z, kk.z, a00); a01 = fmaf(xa.w, kk.w, a01);
        a10 = fmaf(xb.x, kk.x, a10); a11 = fmaf(xb.y, kk.y, a11);
        a10 = fmaf(xb.z, kk.z, a10); a11 = fmaf(xb.w, kk.w, a11);
    }
    float s0 = a00 + a01;
    float s1 = a10 + a11;

    #pragma unroll
    for (int off = 16; off > 0; off >>= 1) {
        s0 += __shfl_down_sync(0xffffffffu, s0, off);
        s1 += __shfl_down_sync(0xffffffffu, s1, off);
    }

    __shared__ float red0[8], red1[8];
    int w = threadIdx.x >> 5, l = threadIdx.x & 31;
    if (l == 0) { red0[w] = s0; red1[w] = s1; }
    __syncthreads();
    if (threadIdx.x == 0) {
        float t0 = 0.0f, t1 = 0.0f;
        #pragma unroll
        for (int i = 0; i < 8; i++) { t0 += red0[i]; t1 += red1[i]; }
        out[r0]     = t0;
        out[r0 + 1] = t1;
    }
}

extern "C" void kernel_launch(void* const* d_in, const int* in_sizes, int n_in,
                              void* d_out, int out_size)
{
    const float* X = (const float*)d_in[0];
    const void*  F = d_in[1];

    prep_kernel<<<1, NTH>>>(
        (const float*)d_in[2], (const float*)d_in[3], (const float*)d_in[4],
        (const float*)d_in[5], (const float*)d_in[6], (const float*)d_in[7], F);

    int rows = in_sizes[0] / TLEN;
    gemv_kernel<<<rows / 2, 256>>>(X, (float*)d_out);
}